// round 12
// baseline (speedup 1.0000x reference)
#include <cuda_runtime.h>
#include <math.h>

#define KC       10
#define BT       256
#define NC       1152
#define ICC      8
#define OC       16
#define BTILE    2
#define NTHREADS 512          // 16 warps -> 4/SMSP -> 128-reg budget
#define NWARP    16
#define JQ       9            // rows kept per thread after merge

struct SmemLayout {
    float sred[NWARP][BTILE][OC];       // per-warp s partials
    float zred[NWARP][BTILE];           // per-warp Z partials
    alignas(16) float vsum[BTILE][OC];  // running sum of v's (b_ij = uh . vsum)
};

// Reduce 8 values over the 8 lanes sharing this oq (lane bits 2,3,4).
// Splitting butterfly: 7 SHFL-adds. Returns fully reduced value; *Lp in [0,8).
__device__ __forceinline__ float reduce8q(const float a[8], int lane, int* Lp) {
    const bool s1 = lane & 4, s2 = lane & 8, s3 = lane & 16;
    float t4[4], t2[2], r;
    #pragma unroll
    for (int j = 0; j < 4; j++) {
        const float send = s1 ? a[j]     : a[4 + j];
        const float keep = s1 ? a[4 + j] : a[j];
        t4[j] = keep + __shfl_xor_sync(0xffffffffu, send, 4);
    }
    #pragma unroll
    for (int j = 0; j < 2; j++) {
        const float send = s2 ? t4[j]     : t4[2 + j];
        const float keep = s2 ? t4[2 + j] : t4[j];
        t2[j] = keep + __shfl_xor_sync(0xffffffffu, send, 8);
    }
    {
        const float send = s3 ? t2[0] : t2[1];
        const float keep = s3 ? t2[1] : t2[0];
        r = keep + __shfl_xor_sync(0xffffffffu, send, 16);
    }
    *Lp = (s1 ? 4 : 0) | (s2 ? 2 : 0) | (s3 ? 1 : 0);
    return r;
}

// Every lane stores its reduced (b, comp) partial: L = 4*b + c, o = 4*oq + c.
__device__ __forceinline__ void store_sred(SmemLayout* sm, int w, int oq, int L, float v) {
    sm->sred[w][L >> 2][4 * oq + (L & 3)] = v;
}

// Each row's c is replicated over its 4 oq-lanes -> x0.25.
__device__ __forceinline__ void store_zred(SmemLayout* sm, int w, int lane,
                                           float z0, float z1) {
    const float send = (lane & 1) ? z0 : z1;
    const float keep = (lane & 1) ? z1 : z0;
    float zz = keep + __shfl_xor_sync(0xffffffffu, send, 1);
    #pragma unroll
    for (int sft = 2; sft <= 16; sft <<= 1)
        zz += __shfl_xor_sync(0xffffffffu, zz, sft);
    if (lane < 2) sm->zred[w][lane] = 0.25f * zz;
}

// 32-thread stage: combine warp partials, normalize, squash, accumulate vsum.
__device__ __forceinline__ void squash_stage(SmemLayout* sm, int t, bool uniform,
                                             bool first, bool writeOut,
                                             float* out, int k, int b0) {
    if (t < 32) {
        const int b = t >> 4, o = t & 15;
        float s = 0.f;
        #pragma unroll
        for (int w = 0; w < NWARP; w++) s += sm->sred[w][b][o];
        float Z;
        if (uniform) {
            Z = (float)NC;
        } else {
            Z = 0.f;
            #pragma unroll
            for (int w = 0; w < NWARP; w++) Z += sm->zred[w][b];
        }
        s /= Z;
        float sq = s * s;
        #pragma unroll
        for (int sft = 1; sft < 16; sft <<= 1)
            sq += __shfl_xor_sync(0xffffffffu, sq, sft);
        const float v = s * sqrtf(sq) / (1.0f + sq);   // squash
        sm->vsum[b][o] = first ? v : (sm->vsum[b][o] + v);
        if (writeOut) out[((size_t)k * BT + b0 + b) * OC + o] = v;
    }
    __syncthreads();
}

__global__ __launch_bounds__(NTHREADS, 1)
void caps_routing_kernel(const float* __restrict__ u, const float* __restrict__ W,
                         float* __restrict__ out) {
    __shared__ SmemLayout sm;

    const int k    = blockIdx.y;
    const int b0   = blockIdx.x * BTILE;
    const int t    = threadIdx.x;
    const int lane = t & 31, w = t >> 5;
    const int oq   = t & 3;              // comps [4oq, 4oq+4)
    const int ip   = (t >> 2) & 1;       // i-parity: this thread handles i = 2s + ip
    const int r    = t >> 3;             // 0..63

    // Register-resident u_hat quarters, both batch elements: 2 x 9 x 4 = 72 regs.
    // Thread keeps rows n = r + 64*ip + 128*m, m = 0..8.
    float4 uh[BTILE][JQ];

    // ---- Phase 1: dense-wavefront W loads (i = 2s+ip => warp LDG covers full
    //      128B lines), partner-merge per row; fuse iter-0 s-sum ----
    {
        // W chunk for (n, s): float offset n*128 + s*32 + ip*16 + oq*4
        const float* Wk  = W + (size_t)k * NC * ICC * OC + ip * 16 + oq * 4;
        const float* ub0 = u + (size_t)b0 * NC * ICC + ip * 4;   // floats 4ip..4ip+3
        const float* ub1 = ub0 + (size_t)NC * ICC;
        float4 s0 = make_float4(0.f,0.f,0.f,0.f), s1 = make_float4(0.f,0.f,0.f,0.f);
        #pragma unroll
        for (int j = 0; j < 2 * JQ; j++) {
            const int n = r + 64 * j;
            // u quad-broadcast loads: warp covers 4 consecutive 32B rows = 1 line
            const float4 uqa = *(const float4*)(ub0 + (size_t)n * ICC);
            const float4 uqb = *(const float4*)(ub1 + (size_t)n * ICC);
            // exchange with xor-4 partner to assemble i = {2s+ip} scalars:
            // ip=0 needs partner's floats {4,6}; ip=1 needs partner's {1,3}
            const float ra1 = __shfl_xor_sync(0xffffffffu, ip ? uqa.x : uqa.y, 4);
            const float ra2 = __shfl_xor_sync(0xffffffffu, ip ? uqa.z : uqa.w, 4);
            const float rb1 = __shfl_xor_sync(0xffffffffu, ip ? uqb.x : uqb.y, 4);
            const float rb2 = __shfl_xor_sync(0xffffffffu, ip ? uqb.z : uqb.w, 4);
            float usA[4], usB[4];
            if (ip) { usA[0]=ra1; usA[1]=ra2; usA[2]=uqa.y; usA[3]=uqa.w;
                      usB[0]=rb1; usB[1]=rb2; usB[2]=uqb.y; usB[3]=uqb.w; }
            else    { usA[0]=uqa.x; usA[1]=uqa.z; usA[2]=ra1; usA[3]=ra2;
                      usB[0]=uqb.x; usB[1]=uqb.z; usB[2]=rb1; usB[3]=rb2; }
            float4 pa = make_float4(0.f,0.f,0.f,0.f);
            float4 pb = make_float4(0.f,0.f,0.f,0.f);
            const float* wp = Wk + (size_t)n * ICC * OC;
            #pragma unroll
            for (int s = 0; s < 4; s++) {
                const float4 wv = *(const float4*)(wp + s * 32);  // i = 2s+ip chunk
                pa.x = fmaf(wv.x, usA[s], pa.x); pa.y = fmaf(wv.y, usA[s], pa.y);
                pa.z = fmaf(wv.z, usA[s], pa.z); pa.w = fmaf(wv.w, usA[s], pa.w);
                pb.x = fmaf(wv.x, usB[s], pb.x); pb.y = fmaf(wv.y, usB[s], pb.y);
                pb.z = fmaf(wv.z, usB[s], pb.z); pb.w = fmaf(wv.w, usB[s], pb.w);
            }
            // merge complementary i-halves with xor-4 partner (sum is symmetric)
            pa.x += __shfl_xor_sync(0xffffffffu, pa.x, 4);
            pa.y += __shfl_xor_sync(0xffffffffu, pa.y, 4);
            pa.z += __shfl_xor_sync(0xffffffffu, pa.z, 4);
            pa.w += __shfl_xor_sync(0xffffffffu, pa.w, 4);
            pb.x += __shfl_xor_sync(0xffffffffu, pb.x, 4);
            pb.y += __shfl_xor_sync(0xffffffffu, pb.y, 4);
            pb.z += __shfl_xor_sync(0xffffffffu, pb.z, 4);
            pb.w += __shfl_xor_sync(0xffffffffu, pb.w, 4);
            if ((j & 1) == ip) {              // keeper stores + accumulates iter-0 sum
                uh[0][j >> 1] = pa; uh[1][j >> 1] = pb;
                s0.x += pa.x; s0.y += pa.y; s0.z += pa.z; s0.w += pa.w;
                s1.x += pb.x; s1.y += pb.y; s1.z += pb.z; s1.w += pb.w;
            }
        }
        const float sa[8] = {s0.x, s0.y, s0.z, s0.w, s1.x, s1.y, s1.z, s1.w};
        int L; const float sv = reduce8q(sa, lane, &L);
        store_sred(&sm, w, oq, L, sv);
    }
    __syncthreads();

    // ---- Iteration 0: b_ij = 0 => c uniform; s already reduced ----
    squash_stage(&sm, t, /*uniform=*/true, /*first=*/true, /*writeOut=*/false, out, k, b0);

    // ---- Iterations 1,2: p = uh . vsum (b_ij linear in uh -> no logit storage) ----
    #pragma unroll 1
    for (int iter = 1; iter < 3; iter++) {
        const float4 v0 = *(const float4*)&sm.vsum[0][4 * oq];   // 16B-aligned
        const float4 v1 = *(const float4*)&sm.vsum[1][4 * oq];
        float4 sc0 = make_float4(0.f,0.f,0.f,0.f), sc1 = make_float4(0.f,0.f,0.f,0.f);
        float z0 = 0.f, z1 = 0.f;
        #pragma unroll
        for (int j = 0; j < JQ; j++) {
            const float4 h0 = uh[0][j], h1 = uh[1][j];
            float pa = h0.x * v0.x;
            pa = fmaf(h0.y, v0.y, pa); pa = fmaf(h0.z, v0.z, pa); pa = fmaf(h0.w, v0.w, pa);
            float pb = h1.x * v1.x;
            pb = fmaf(h1.y, v1.y, pb); pb = fmaf(h1.z, v1.z, pb); pb = fmaf(h1.w, v1.w, pb);
            pa += __shfl_xor_sync(0xffffffffu, pa, 1);   // join 4 quarter-dots
            pb += __shfl_xor_sync(0xffffffffu, pb, 1);
            pa += __shfl_xor_sync(0xffffffffu, pa, 2);
            pb += __shfl_xor_sync(0xffffffffu, pb, 2);
            const float c0 = __expf(pa);   // softmax shift-invariant; |p| << 88
            const float c1 = __expf(pb);
            z0 += c0; z1 += c1;
            sc0.x = fmaf(c0, h0.x, sc0.x); sc0.y = fmaf(c0, h0.y, sc0.y);
            sc0.z = fmaf(c0, h0.z, sc0.z); sc0.w = fmaf(c0, h0.w, sc0.w);
            sc1.x = fmaf(c1, h1.x, sc1.x); sc1.y = fmaf(c1, h1.y, sc1.y);
            sc1.z = fmaf(c1, h1.z, sc1.z); sc1.w = fmaf(c1, h1.w, sc1.w);
        }
        const float sa[8] = {sc0.x, sc0.y, sc0.z, sc0.w, sc1.x, sc1.y, sc1.z, sc1.w};
        int L; const float sv = reduce8q(sa, lane, &L);
        store_sred(&sm, w, oq, L, sv);
        store_zred(&sm, w, lane, z0, z1);
        __syncthreads();

        squash_stage(&sm, t, /*uniform=*/false, /*first=*/false,
                     /*writeOut=*/(iter == 2), out, k, b0);
    }
}

extern "C" void kernel_launch(void* const* d_in, const int* in_sizes, int n_in,
                              void* d_out, int out_size) {
    const float* u = (const float*)d_in[0];   // [256, 1152, 8]
    const float* W = (const float*)d_in[1];   // [10, 1152, 8, 16]
    float* out = (float*)d_out;               // [10, 256, 1, 1, 16]

    dim3 grid(BT / BTILE, KC);                // 128 x 10 = 1280 CTAs
    caps_routing_kernel<<<grid, NTHREADS>>>(u, W, out);
}